// round 2
// baseline (speedup 1.0000x reference)
#include <cuda_runtime.h>
#include <math.h>
#include <stdint.h>

#define VSZ 50000
#define ESZ 256
#define HSZ 512
#define BSZ 128
#define LSZ 400
#define TSZ 100
#define K3H 1536

// ---------------- scratch (device globals; no allocation allowed) ----------------
__device__ float g_te[BSZ * HSZ];
__device__ float g_td[BSZ * HSZ];
__device__ float g_alpha[BSZ * LSZ];
__device__ float g_nh[BSZ * K3H];     // [c_t_e | h | c_t_d]
__device__ float g_p[BSZ];            // pointer_prob
__device__ float g_lse[BSZ];          // max + log(sum exp)

__device__ __forceinline__ float warp_sum(float v) {
    #pragma unroll
    for (int o = 16; o > 0; o >>= 1) v += __shfl_down_sync(0xffffffffu, v, o);
    return v;
}

// ---------------- K1: embed + GRU + te/td projections (one block per b) ----------
__global__ void __launch_bounds__(256) k_gru(
    const int* __restrict__ inputs,       // (1,B)
    const float* __restrict__ hidden,     // (1,B,H)
    const float* __restrict__ emb,        // (V,E)
    const float* __restrict__ W_ih,       // (3H,E)
    const float* __restrict__ W_hh,       // (3H,H)
    const float* __restrict__ b_ih, const float* __restrict__ b_hh,
    const float* __restrict__ W_ae, const float* __restrict__ b_ae,
    const float* __restrict__ W_ad, const float* __restrict__ b_ad,
    float* __restrict__ h_out)            // d_out h region (B,H)
{
    __shared__ float sx[ESZ];
    __shared__ float sh[HSZ];
    __shared__ float sgi[K3H];
    __shared__ float sgh[K3H];
    __shared__ float shn[HSZ];

    const int b = blockIdx.x;
    const int t = threadIdx.x;
    const int w = t >> 5, lane = t & 31;

    const int tok = inputs[b];
    sx[t] = emb[(size_t)tok * ESZ + t];                 // t < 256 == E
    sh[t] = hidden[b * HSZ + t];
    sh[t + 256] = hidden[b * HSZ + t + 256];
    __syncthreads();

    // gi[j], gh[j] for j in [0,3H): warp-per-row
    for (int j = w; j < K3H; j += 8) {
        const float* wi = W_ih + (size_t)j * ESZ;
        const float* wh = W_hh + (size_t)j * HSZ;
        float si = 0.f, sg = 0.f;
        #pragma unroll
        for (int i = lane; i < ESZ; i += 32) si += wi[i] * sx[i];
        #pragma unroll
        for (int i = lane; i < HSZ; i += 32) sg += wh[i] * sh[i];
        si = warp_sum(si); sg = warp_sum(sg);
        if (lane == 0) { sgi[j] = si + b_ih[j]; sgh[j] = sg + b_hh[j]; }
    }
    __syncthreads();

    // gates
    for (int hh = t; hh < HSZ; hh += 256) {
        float r = 1.f / (1.f + expf(-(sgi[hh] + sgh[hh])));
        float z = 1.f / (1.f + expf(-(sgi[hh + HSZ] + sgh[hh + HSZ])));
        float n = tanhf(sgi[hh + 2 * HSZ] + r * sgh[hh + 2 * HSZ]);
        float hn = (1.f - z) * n + z * sh[hh];
        shn[hh] = hn;
        h_out[b * HSZ + hh] = hn;
        g_nh[b * K3H + HSZ + hh] = hn;   // middle third of new_hidden
    }
    __syncthreads();

    // te = h @ W_ae^T + b_ae ; td = h @ W_ad^T + b_ad
    for (int j = w; j < HSZ; j += 8) {
        const float* wa = W_ae + (size_t)j * HSZ;
        const float* wd = W_ad + (size_t)j * HSZ;
        float a = 0.f, d = 0.f;
        #pragma unroll
        for (int i = lane; i < HSZ; i += 32) {
            float hv = shn[i];
            a += wa[i] * hv;
            d += wd[i] * hv;
        }
        a = warp_sum(a); d = warp_sum(d);
        if (lane == 0) {
            g_te[b * HSZ + j] = a + b_ae[j];
            g_td[b * HSZ + j] = d + b_ad[j];
        }
    }
}

// ---------------- K2: attention (scores -> softmax -> context), one block per b ---
// USE_TD selects the device-global query buffer INSIDE device code (passing
// __device__ globals as host-side kernel args is UB — that was the R1 bug).
template<int S, int NHOFF, bool USE_TD, bool MASK, bool STORE_ALPHA>
__global__ void __launch_bounds__(512) k_attn(
    const float* __restrict__ kv,       // (S,B,H)
    const int* __restrict__ lengths)
{
    __shared__ float sq[HSZ];
    __shared__ float sc[S];
    __shared__ float sred[512];

    const int b = blockIdx.x;
    const int t = threadIdx.x;
    const int w = t >> 5, lane = t & 31;

    const float* q = USE_TD ? g_td : g_te;
    sq[t] = q[b * HSZ + t];
    __syncthreads();

    int len = MASK ? lengths[b] : S;

    // scores
    for (int l = w; l < S; l += 16) {
        const float* row = kv + ((size_t)l * BSZ + b) * HSZ;
        float s = 0.f;
        #pragma unroll 4
        for (int i = lane; i < HSZ; i += 32) s += row[i] * sq[i];
        s = warp_sum(s);
        if (lane == 0) {
            if (MASK && (S < len) && (l >= len)) s = -INFINITY;
            sc[l] = s;
        }
    }
    __syncthreads();

    // softmax over S
    float v = (t < S) ? sc[t] : -INFINITY;
    sred[t] = v; __syncthreads();
    #pragma unroll
    for (int o = 256; o > 0; o >>= 1) { if (t < o) sred[t] = fmaxf(sred[t], sred[t + o]); __syncthreads(); }
    float m = sred[0]; __syncthreads();
    float e = (t < S) ? expf(sc[t] - m) : 0.f;
    sred[t] = e; __syncthreads();
    #pragma unroll
    for (int o = 256; o > 0; o >>= 1) { if (t < o) sred[t] += sred[t + o]; __syncthreads(); }
    float ssum = sred[0]; __syncthreads();
    if (t < S) {
        float a = e / ssum;
        sc[t] = a;
        if (STORE_ALPHA) g_alpha[b * S + t] = a;
    }
    __syncthreads();

    // context: c[h] = sum_l alpha[l] * kv[l,b,h]
    float c = 0.f;
    const float* base = kv + (size_t)b * HSZ + t;
    #pragma unroll 4
    for (int l = 0; l < S; l++) c += sc[l] * base[(size_t)l * BSZ * HSZ];
    g_nh[b * K3H + NHOFF + t] = c;
}

// ---------------- K3: pointer prob (warp per b) -----------------------------------
__global__ void __launch_bounds__(256) k_pointer(
    const float* __restrict__ W_ptr, const float* __restrict__ b_ptr)
{
    int gw = (blockIdx.x * blockDim.x + threadIdx.x) >> 5;
    int lane = threadIdx.x & 31;
    if (gw >= BSZ) return;
    float s = 0.f;
    #pragma unroll 4
    for (int i = lane; i < K3H; i += 32) s += g_nh[gw * K3H + i] * W_ptr[i];
    s = warp_sum(s);
    if (lane == 0) g_p[gw] = s + b_ptr[0];
}

// ---------------- K4: big GEMM: logits = nh @ W_out^T + b_out ---------------------
#define BM 128
#define BN 128
#define BK 32
__global__ void __launch_bounds__(256) k_gemm(
    const float* __restrict__ W,        // (V,3H)
    const float* __restrict__ bias,     // (V,)
    float* __restrict__ out)            // (B,V) logits
{
    __shared__ float As[BK][BM];        // As[k][m] (m = batch row)
    __shared__ float Ws[BK][BN + 4];    // Ws[k][n]

    const int tid = threadIdx.x;
    const int n0 = blockIdx.x * BN;
    const int tx = tid & 15;            // n direction
    const int ty = tid >> 4;            // m direction

    float acc[8][8];
    #pragma unroll
    for (int i = 0; i < 8; i++)
        #pragma unroll
        for (int j = 0; j < 8; j++) acc[i][j] = 0.f;

    for (int k0 = 0; k0 < K3H; k0 += BK) {
        #pragma unroll
        for (int it = 0; it < 4; it++) {
            int idx = tid + it * 256;           // 0..1023
            int m = idx >> 3;
            int kq = (idx & 7) << 2;
            float4 v = *(const float4*)(g_nh + (size_t)m * K3H + k0 + kq);
            As[kq + 0][m] = v.x; As[kq + 1][m] = v.y;
            As[kq + 2][m] = v.z; As[kq + 3][m] = v.w;
        }
        #pragma unroll
        for (int it = 0; it < 4; it++) {
            int idx = tid + it * 256;
            int n = idx >> 3;
            int kq = (idx & 7) << 2;
            int gn = n0 + n;
            float4 v = (gn < VSZ) ? *(const float4*)(W + (size_t)gn * K3H + k0 + kq)
                                  : make_float4(0.f, 0.f, 0.f, 0.f);
            Ws[kq + 0][n] = v.x; Ws[kq + 1][n] = v.y;
            Ws[kq + 2][n] = v.z; Ws[kq + 3][n] = v.w;
        }
        __syncthreads();

        #pragma unroll
        for (int kk = 0; kk < BK; kk++) {
            float4 a0 = *(const float4*)&As[kk][ty * 8];
            float4 a1 = *(const float4*)&As[kk][ty * 8 + 4];
            float4 w0 = *(const float4*)&Ws[kk][tx * 8];
            float4 w1 = *(const float4*)&Ws[kk][tx * 8 + 4];
            float af[8] = {a0.x, a0.y, a0.z, a0.w, a1.x, a1.y, a1.z, a1.w};
            float wf[8] = {w0.x, w0.y, w0.z, w0.w, w1.x, w1.y, w1.z, w1.w};
            #pragma unroll
            for (int i = 0; i < 8; i++)
                #pragma unroll
                for (int j = 0; j < 8; j++) acc[i][j] += af[i] * wf[j];
        }
        __syncthreads();
    }

    #pragma unroll
    for (int i = 0; i < 8; i++) {
        int m = ty * 8 + i;
        #pragma unroll
        for (int j = 0; j < 8; j++) {
            int gn = n0 + tx * 8 + j;
            if (gn < VSZ) out[(size_t)m * VSZ + gn] = acc[i][j] + bias[gn];
        }
    }
}

// ---------------- K5: per-row logsumexp over V (block per b) ----------------------
__global__ void __launch_bounds__(1024) k_lse(const float* __restrict__ logits)
{
    __shared__ float sr[1024];
    const int b = blockIdx.x, t = threadIdx.x;
    const float* row = logits + (size_t)b * VSZ;
    float m = -INFINITY;
    for (int i = t; i < VSZ; i += 1024) m = fmaxf(m, row[i]);
    sr[t] = m; __syncthreads();
    #pragma unroll
    for (int o = 512; o > 0; o >>= 1) { if (t < o) sr[t] = fmaxf(sr[t], sr[t + o]); __syncthreads(); }
    m = sr[0]; __syncthreads();
    float s = 0.f;
    for (int i = t; i < VSZ; i += 1024) s += expf(row[i] - m);
    sr[t] = s; __syncthreads();
    #pragma unroll
    for (int o = 512; o > 0; o >>= 1) { if (t < o) sr[t] += sr[t + o]; __syncthreads(); }
    if (t == 0) g_lse[b] = m + logf(sr[0]);
}

// ---------------- K6: finalize: out = (1-p) * (logit - lse) -----------------------
__global__ void __launch_bounds__(256) k_finalize(float* __restrict__ out)
{
    size_t i = (size_t)blockIdx.x * blockDim.x + threadIdx.x;
    if (i >= (size_t)BSZ * VSZ) return;
    int b = (int)(i / VSZ);
    out[i] = (1.f - g_p[b]) * (out[i] - g_lse[b]);
}

// ---------------- K7: pointer scatter add -----------------------------------------
__global__ void __launch_bounds__(256) k_scatter(
    float* __restrict__ out, const int* __restrict__ enc_inputs)
{
    int i = blockIdx.x * blockDim.x + threadIdx.x;
    if (i >= BSZ * LSZ) return;
    int b = i & (BSZ - 1);
    int l = i >> 7;                   // i / 128
    int tok = enc_inputs[l * BSZ + b];
    atomicAdd(out + (size_t)b * VSZ + tok, g_p[b] * g_alpha[b * LSZ + l]);
}

// ---------------- launch ----------------------------------------------------------
extern "C" void kernel_launch(void* const* d_in, const int* in_sizes, int n_in,
                              void* d_out, int out_size)
{
    const int*   inputs      = (const int*)  d_in[0];
    const float* hidden      = (const float*)d_in[1];
    const float* enc_hidden  = (const float*)d_in[2];
    const int*   enc_lengths = (const int*)  d_in[3];
    const float* prev_w      = (const float*)d_in[4];
    const float* dec_hidden  = (const float*)d_in[5];
    const int*   enc_inputs  = (const int*)  d_in[6];

    // Robust weight-base detection: emb has the unique size V*E = 12,800,000.
    // This absorbs time_step being materialized (or not) as input index 7.
    int wbase = 7;
    for (int i = 7; i < n_in; i++) {
        if (in_sizes[i] == VSZ * ESZ) { wbase = i; break; }
    }
    const float* emb   = (const float*)d_in[wbase + 0];
    const float* W_ih  = (const float*)d_in[wbase + 1];
    const float* W_hh  = (const float*)d_in[wbase + 2];
    const float* b_ih  = (const float*)d_in[wbase + 3];
    const float* b_hh  = (const float*)d_in[wbase + 4];
    const float* W_ae  = (const float*)d_in[wbase + 5];
    const float* b_ae  = (const float*)d_in[wbase + 6];
    const float* W_ad  = (const float*)d_in[wbase + 7];
    const float* b_ad  = (const float*)d_in[wbase + 8];
    const float* W_ptr = (const float*)d_in[wbase + 9];
    const float* b_ptr = (const float*)d_in[wbase + 10];
    const float* W_out = (const float*)d_in[wbase + 11];
    const float* b_out = (const float*)d_in[wbase + 12];

    float* out     = (float*)d_out;                    // (B,V) final_output
    float* h_out   = out + (size_t)BSZ * VSZ;          // (1,B,H)
    float* pw_out  = h_out + (size_t)BSZ * HSZ;        // (B,1,L)

    k_gru<<<BSZ, 256>>>(inputs, hidden, emb, W_ih, W_hh, b_ih, b_hh,
                        W_ae, b_ae, W_ad, b_ad, h_out);

    k_attn<LSZ, 0,       false, true,  true ><<<BSZ, 512>>>(enc_hidden, enc_lengths);
    k_attn<TSZ, 2 * HSZ, true,  false, false><<<BSZ, 512>>>(dec_hidden, enc_lengths);

    k_pointer<<<16, 256>>>(W_ptr, b_ptr);

    k_gemm<<<(VSZ + BN - 1) / BN, 256>>>(W_out, b_out, out);

    k_lse<<<BSZ, 1024>>>(out);

    k_finalize<<<(int)(((size_t)BSZ * VSZ + 255) / 256), 256>>>(out);

    k_scatter<<<(BSZ * LSZ + 255) / 256, 256>>>(out, enc_inputs);

    cudaMemcpyAsync(pw_out, prev_w, (size_t)BSZ * LSZ * sizeof(float),
                    cudaMemcpyDeviceToDevice, 0);
}

// round 3
// speedup vs baseline: 1.5294x; 1.5294x over previous
#include <cuda_runtime.h>
#include <math.h>
#include <stdint.h>

#define VSZ 50000
#define ESZ 256
#define HSZ 512
#define BSZ 128
#define LSZ 400
#define TSZ 100
#define K3H 1536

// ---------------- scratch (device globals; no allocation allowed) ----------------
__device__ float g_te[BSZ * HSZ];
__device__ float g_td[BSZ * HSZ];
__device__ float g_alpha[BSZ * LSZ];
__device__ float g_nh[BSZ * K3H];     // [c_t_e | h | c_t_d]
__device__ float g_p[BSZ];            // pointer_prob
__device__ float g_lse[BSZ];          // max + log(sum exp)

__device__ __forceinline__ float warp_sum(float v) {
    #pragma unroll
    for (int o = 16; o > 0; o >>= 1) v += __shfl_down_sync(0xffffffffu, v, o);
    return v;
}

// ---------------- K1: embed + GRU + te/td projections (one block per b) ----------
__global__ void __launch_bounds__(256) k_gru(
    const int* __restrict__ inputs,
    const float* __restrict__ hidden,
    const float* __restrict__ emb,
    const float* __restrict__ W_ih,
    const float* __restrict__ W_hh,
    const float* __restrict__ b_ih, const float* __restrict__ b_hh,
    const float* __restrict__ W_ae, const float* __restrict__ b_ae,
    const float* __restrict__ W_ad, const float* __restrict__ b_ad,
    float* __restrict__ h_out)
{
    __shared__ float sx[ESZ];
    __shared__ float sh[HSZ];
    __shared__ float sgi[K3H];
    __shared__ float sgh[K3H];
    __shared__ float shn[HSZ];

    const int b = blockIdx.x;
    const int t = threadIdx.x;
    const int w = t >> 5, lane = t & 31;

    const int tok = inputs[b];
    sx[t] = emb[(size_t)tok * ESZ + t];
    sh[t] = hidden[b * HSZ + t];
    sh[t + 256] = hidden[b * HSZ + t + 256];
    __syncthreads();

    for (int j = w; j < K3H; j += 8) {
        const float* wi = W_ih + (size_t)j * ESZ;
        const float* wh = W_hh + (size_t)j * HSZ;
        float si = 0.f, sg = 0.f;
        #pragma unroll
        for (int i = lane; i < ESZ; i += 32) si += wi[i] * sx[i];
        #pragma unroll
        for (int i = lane; i < HSZ; i += 32) sg += wh[i] * sh[i];
        si = warp_sum(si); sg = warp_sum(sg);
        if (lane == 0) { sgi[j] = si + b_ih[j]; sgh[j] = sg + b_hh[j]; }
    }
    __syncthreads();

    for (int hh = t; hh < HSZ; hh += 256) {
        float r = 1.f / (1.f + expf(-(sgi[hh] + sgh[hh])));
        float z = 1.f / (1.f + expf(-(sgi[hh + HSZ] + sgh[hh + HSZ])));
        float n = tanhf(sgi[hh + 2 * HSZ] + r * sgh[hh + 2 * HSZ]);
        float hn = (1.f - z) * n + z * sh[hh];
        shn[hh] = hn;
        h_out[b * HSZ + hh] = hn;
        g_nh[b * K3H + HSZ + hh] = hn;
    }
    __syncthreads();

    for (int j = w; j < HSZ; j += 8) {
        const float* wa = W_ae + (size_t)j * HSZ;
        const float* wd = W_ad + (size_t)j * HSZ;
        float a = 0.f, d = 0.f;
        #pragma unroll
        for (int i = lane; i < HSZ; i += 32) {
            float hv = shn[i];
            a += wa[i] * hv;
            d += wd[i] * hv;
        }
        a = warp_sum(a); d = warp_sum(d);
        if (lane == 0) {
            g_te[b * HSZ + j] = a + b_ae[j];
            g_td[b * HSZ + j] = d + b_ad[j];
        }
    }
}

// ---------------- K2: attention -----------------------------------------------
template<int S, int NHOFF, bool USE_TD, bool MASK, bool STORE_ALPHA>
__global__ void __launch_bounds__(512) k_attn(
    const float* __restrict__ kv,
    const int* __restrict__ lengths)
{
    __shared__ float sq[HSZ];
    __shared__ float sc[S];
    __shared__ float sred[512];

    const int b = blockIdx.x;
    const int t = threadIdx.x;
    const int w = t >> 5, lane = t & 31;

    const float* q = USE_TD ? g_td : g_te;
    sq[t] = q[b * HSZ + t];
    __syncthreads();

    int len = MASK ? lengths[b] : S;

    for (int l = w; l < S; l += 16) {
        const float* row = kv + ((size_t)l * BSZ + b) * HSZ;
        float s = 0.f;
        #pragma unroll 4
        for (int i = lane; i < HSZ; i += 32) s += row[i] * sq[i];
        s = warp_sum(s);
        if (lane == 0) {
            if (MASK && (S < len) && (l >= len)) s = -INFINITY;
            sc[l] = s;
        }
    }
    __syncthreads();

    float v = (t < S) ? sc[t] : -INFINITY;
    sred[t] = v; __syncthreads();
    #pragma unroll
    for (int o = 256; o > 0; o >>= 1) { if (t < o) sred[t] = fmaxf(sred[t], sred[t + o]); __syncthreads(); }
    float m = sred[0]; __syncthreads();
    float e = (t < S) ? expf(sc[t] - m) : 0.f;
    sred[t] = e; __syncthreads();
    #pragma unroll
    for (int o = 256; o > 0; o >>= 1) { if (t < o) sred[t] += sred[t + o]; __syncthreads(); }
    float ssum = sred[0]; __syncthreads();
    if (t < S) {
        float a = e / ssum;
        sc[t] = a;
        if (STORE_ALPHA) g_alpha[b * S + t] = a;
    }
    __syncthreads();

    float c = 0.f;
    const float* base = kv + (size_t)b * HSZ + t;
    #pragma unroll 4
    for (int l = 0; l < S; l++) c += sc[l] * base[(size_t)l * BSZ * HSZ];
    g_nh[b * K3H + NHOFF + t] = c;
}

// ---------------- K3: pointer prob (block per b) --------------------------------
__global__ void __launch_bounds__(256) k_pointer(
    const float* __restrict__ W_ptr, const float* __restrict__ b_ptr)
{
    __shared__ float sred[8];
    const int b = blockIdx.x;
    const int t = threadIdx.x;
    const int w = t >> 5, lane = t & 31;
    float s = 0.f;
    #pragma unroll
    for (int i = t; i < K3H; i += 256) s += g_nh[b * K3H + i] * W_ptr[i];
    s = warp_sum(s);
    if (lane == 0) sred[w] = s;
    __syncthreads();
    if (t == 0) {
        float tot = 0.f;
        #pragma unroll
        for (int i = 0; i < 8; i++) tot += sred[i];
        g_p[b] = tot + b_ptr[0];
    }
}

// ---------------- K4: GEMM on tensor cores (tf32 mma.sync) ----------------------
// logits[B=128, V] = nh[128, K3H] @ W^T[V, K3H] + bias
// Block tile 128(M) x 128(N) x 32(K). 8 warps (2m x 4n), warp tile 64x32.
#define GBN 128
#define GBK 32
#define GST 36          // smem row stride in f32 words: banks = 4g+tig, conflict-free
#define GKIT (K3H / GBK)

__device__ __forceinline__ uint32_t f2tf32(float x) {
    uint32_t u;
    asm("cvt.rna.tf32.f32 %0, %1;" : "=r"(u) : "f"(x));
    return u;
}

__device__ __forceinline__ void mma_tf32(float* d, const uint32_t* a, const uint32_t* b) {
    asm volatile(
        "mma.sync.aligned.m16n8k8.row.col.f32.tf32.tf32.f32 "
        "{%0,%1,%2,%3}, {%4,%5,%6,%7}, {%8,%9}, {%0,%1,%2,%3};\n"
        : "+f"(d[0]), "+f"(d[1]), "+f"(d[2]), "+f"(d[3])
        : "r"(a[0]), "r"(a[1]), "r"(a[2]), "r"(a[3]), "r"(b[0]), "r"(b[1]));
}

__global__ void __launch_bounds__(256, 1) k_gemm_tc(
    const float* __restrict__ W,        // (V, K3H)
    const float* __restrict__ bias,     // (V,)
    float* __restrict__ out)            // (B, V)
{
    __shared__ uint32_t sa[BSZ * GST];  // A tile: [m][k], tf32 bits
    __shared__ uint32_t sb[GBN * GST];  // B tile: [n][k], tf32 bits

    const int tid  = threadIdx.x;
    const int n0   = blockIdx.x * GBN;
    const int warp = tid >> 5, lane = tid & 31;
    const int g    = lane >> 2, tig = lane & 3;
    const int wm   = (warp >> 2) * 64;   // 0 / 64
    const int wn   = (warp & 3) * 32;    // 0 / 32 / 64 / 96

    // staging mapping: thread t covers row (t>>1), k-halves of 16
    const int srow = tid >> 1;
    const int skc  = (tid & 1) << 4;
    const int gn_s = n0 + srow;

    float4 ra[4], rb[4];

    auto load_tile = [&](int kt) {
        const float* ap = g_nh + (size_t)srow * K3H + kt + skc;
        #pragma unroll
        for (int q = 0; q < 4; q++) ra[q] = *(const float4*)(ap + 4 * q);
        if (gn_s < VSZ) {
            const float* wp = W + (size_t)gn_s * K3H + kt + skc;
            #pragma unroll
            for (int q = 0; q < 4; q++) rb[q] = *(const float4*)(wp + 4 * q);
        } else {
            #pragma unroll
            for (int q = 0; q < 4; q++) rb[q] = make_float4(0.f, 0.f, 0.f, 0.f);
        }
    };
    auto store_tile = [&]() {
        uint32_t* sap = sa + srow * GST + skc;
        uint32_t* sbp = sb + srow * GST + skc;
        #pragma unroll
        for (int q = 0; q < 4; q++) {
            uint4 ua = { f2tf32(ra[q].x), f2tf32(ra[q].y), f2tf32(ra[q].z), f2tf32(ra[q].w) };
            uint4 ub = { f2tf32(rb[q].x), f2tf32(rb[q].y), f2tf32(rb[q].z), f2tf32(rb[q].w) };
            *(uint4*)(sap + 4 * q) = ua;
            *(uint4*)(sbp + 4 * q) = ub;
        }
    };

    float acc[4][4][4];
    #pragma unroll
    for (int mi = 0; mi < 4; mi++)
        #pragma unroll
        for (int nj = 0; nj < 4; nj++)
            #pragma unroll
            for (int r = 0; r < 4; r++) acc[mi][nj][r] = 0.f;

    load_tile(0);

    for (int it = 0; it < GKIT; ++it) {
        __syncthreads();                 // previous iteration's smem reads done
        store_tile();
        __syncthreads();
        if (it + 1 < GKIT) load_tile((it + 1) * GBK);   // prefetch (overlaps mma)

        #pragma unroll
        for (int ks = 0; ks < 4; ks++) {
            const int k0 = ks * 8;
            uint32_t bf[4][2];
            #pragma unroll
            for (int nj = 0; nj < 4; nj++) {
                const int nb = wn + nj * 8 + g;
                bf[nj][0] = sb[nb * GST + k0 + tig];
                bf[nj][1] = sb[nb * GST + k0 + tig + 4];
            }
            #pragma unroll
            for (int mi = 0; mi < 4; mi++) {
                const int rb0 = wm + mi * 16;
                uint32_t af[4];
                af[0] = sa[(rb0 + g) * GST + k0 + tig];
                af[1] = sa[(rb0 + g + 8) * GST + k0 + tig];
                af[2] = sa[(rb0 + g) * GST + k0 + tig + 4];
                af[3] = sa[(rb0 + g + 8) * GST + k0 + tig + 4];
                #pragma unroll
                for (int nj = 0; nj < 4; nj++) mma_tf32(acc[mi][nj], af, bf[nj]);
            }
        }
    }

    // epilogue: add bias, store
    #pragma unroll
    for (int mi = 0; mi < 4; mi++) {
        const int m = wm + mi * 16 + g;
        #pragma unroll
        for (int nj = 0; nj < 4; nj++) {
            const int gnc = n0 + wn + nj * 8 + 2 * tig;
            if (gnc < VSZ) {
                float2 bv = *(const float2*)(bias + gnc);
                float2 o0 = { acc[mi][nj][0] + bv.x, acc[mi][nj][1] + bv.y };
                float2 o1 = { acc[mi][nj][2] + bv.x, acc[mi][nj][3] + bv.y };
                *(float2*)(out + (size_t)m * VSZ + gnc) = o0;
                *(float2*)(out + (size_t)(m + 8) * VSZ + gnc) = o1;
            }
        }
    }
}

// ---------------- K5: per-row logsumexp over V ---------------------------------
__global__ void __launch_bounds__(1024) k_lse(const float* __restrict__ logits)
{
    __shared__ float sr[1024];
    const int b = blockIdx.x, t = threadIdx.x;
    const float* row = logits + (size_t)b * VSZ;
    float m = -INFINITY;
    for (int i = t; i < VSZ; i += 1024) m = fmaxf(m, row[i]);
    sr[t] = m; __syncthreads();
    #pragma unroll
    for (int o = 512; o > 0; o >>= 1) { if (t < o) sr[t] = fmaxf(sr[t], sr[t + o]); __syncthreads(); }
    m = sr[0]; __syncthreads();
    float s = 0.f;
    for (int i = t; i < VSZ; i += 1024) s += expf(row[i] - m);
    sr[t] = s; __syncthreads();
    #pragma unroll
    for (int o = 512; o > 0; o >>= 1) { if (t < o) sr[t] += sr[t + o]; __syncthreads(); }
    if (t == 0) g_lse[b] = m + logf(sr[0]);
}

// ---------------- K6: finalize -------------------------------------------------
__global__ void __launch_bounds__(256) k_finalize(float* __restrict__ out)
{
    size_t i = (size_t)blockIdx.x * blockDim.x + threadIdx.x;
    if (i >= (size_t)BSZ * VSZ) return;
    int b = (int)(i / VSZ);
    out[i] = (1.f - g_p[b]) * (out[i] - g_lse[b]);
}

// ---------------- K7: pointer scatter add --------------------------------------
__global__ void __launch_bounds__(256) k_scatter(
    float* __restrict__ out, const int* __restrict__ enc_inputs)
{
    int i = blockIdx.x * blockDim.x + threadIdx.x;
    if (i >= BSZ * LSZ) return;
    int b = i & (BSZ - 1);
    int l = i >> 7;
    int tok = enc_inputs[l * BSZ + b];
    atomicAdd(out + (size_t)b * VSZ + tok, g_p[b] * g_alpha[b * LSZ + l]);
}

// ---------------- launch --------------------------------------------------------
extern "C" void kernel_launch(void* const* d_in, const int* in_sizes, int n_in,
                              void* d_out, int out_size)
{
    const int*   inputs      = (const int*)  d_in[0];
    const float* hidden      = (const float*)d_in[1];
    const float* enc_hidden  = (const float*)d_in[2];
    const int*   enc_lengths = (const int*)  d_in[3];
    const float* prev_w      = (const float*)d_in[4];
    const float* dec_hidden  = (const float*)d_in[5];
    const int*   enc_inputs  = (const int*)  d_in[6];

    int wbase = 7;
    for (int i = 7; i < n_in; i++) {
        if (in_sizes[i] == VSZ * ESZ) { wbase = i; break; }
    }
    const float* emb   = (const float*)d_in[wbase + 0];
    const float* W_ih  = (const float*)d_in[wbase + 1];
    const float* W_hh  = (const float*)d_in[wbase + 2];
    const float* b_ih  = (const float*)d_in[wbase + 3];
    const float* b_hh  = (const float*)d_in[wbase + 4];
    const float* W_ae  = (const float*)d_in[wbase + 5];
    const float* b_ae  = (const float*)d_in[wbase + 6];
    const float* W_ad  = (const float*)d_in[wbase + 7];
    const float* b_ad  = (const float*)d_in[wbase + 8];
    const float* W_ptr = (const float*)d_in[wbase + 9];
    const float* b_ptr = (const float*)d_in[wbase + 10];
    const float* W_out = (const float*)d_in[wbase + 11];
    const float* b_out = (const float*)d_in[wbase + 12];

    float* out     = (float*)d_out;
    float* h_out   = out + (size_t)BSZ * VSZ;
    float* pw_out  = h_out + (size_t)BSZ * HSZ;

    k_gru<<<BSZ, 256>>>(inputs, hidden, emb, W_ih, W_hh, b_ih, b_hh,
                        W_ae, b_ae, W_ad, b_ad, h_out);

    k_attn<LSZ, 0,       false, true,  true ><<<BSZ, 512>>>(enc_hidden, enc_lengths);
    k_attn<TSZ, 2 * HSZ, true,  false, false><<<BSZ, 512>>>(dec_hidden, enc_lengths);

    k_pointer<<<BSZ, 256>>>(W_ptr, b_ptr);

    k_gemm_tc<<<(VSZ + GBN - 1) / GBN, 256>>>(W_out, b_out, out);

    k_lse<<<BSZ, 1024>>>(out);

    k_finalize<<<(int)(((size_t)BSZ * VSZ + 255) / 256), 256>>>(out);

    k_scatter<<<(BSZ * LSZ + 255) / 256, 256>>>(out, enc_inputs);

    cudaMemcpyAsync(pw_out, prev_w, (size_t)BSZ * LSZ * sizeof(float),
                    cudaMemcpyDeviceToDevice, 0);
}

// round 11
// speedup vs baseline: 1.6091x; 1.0521x over previous
#include <cuda_runtime.h>
#include <cuda_bf16.h>
#include <math.h>
#include <stdint.h>

#define VSZ 50000
#define ESZ 256
#define HSZ 512
#define BSZ 128
#define LSZ 400
#define TSZ 100
#define K3H 1536

// ---------------- scratch (device globals; no allocation allowed) ----------------
__device__ float g_te[BSZ * HSZ];
__device__ float g_td[BSZ * HSZ];
__device__ float g_alpha[BSZ * LSZ];
__device__ float g_nh[BSZ * K3H];     // [c_t_e | h | c_t_d]
__device__ float g_p[BSZ];            // pointer_prob
__device__ float g_lse[BSZ];          // max + log(sum exp)

__device__ __forceinline__ float warp_sum(float v) {
    #pragma unroll
    for (int o = 16; o > 0; o >>= 1) v += __shfl_down_sync(0xffffffffu, v, o);
    return v;
}

// ---------------- K1: embed + GRU + te/td (2 batch rows per block) ----------------
__global__ void __launch_bounds__(256) k_gru(
    const int* __restrict__ inputs,
    const float* __restrict__ hidden,
    const float* __restrict__ emb,
    const float* __restrict__ W_ih,
    const float* __restrict__ W_hh,
    const float* __restrict__ b_ih, const float* __restrict__ b_hh,
    const float* __restrict__ W_ae, const float* __restrict__ b_ae,
    const float* __restrict__ W_ad, const float* __restrict__ b_ad,
    float* __restrict__ h_out)
{
    __shared__ float sx[2][ESZ];
    __shared__ float sh[2][HSZ];
    __shared__ float sgi[2][K3H];
    __shared__ float sgh[2][K3H];
    __shared__ float shn[2][HSZ];

    const int b0 = blockIdx.x * 2;
    const int t = threadIdx.x;
    const int w = t >> 5, lane = t & 31;

    sx[0][t] = emb[(size_t)inputs[b0] * ESZ + t];
    sx[1][t] = emb[(size_t)inputs[b0 + 1] * ESZ + t];
    #pragma unroll
    for (int i = t; i < 2 * HSZ; i += 256) {
        int u = i >> 9, hh = i & (HSZ - 1);
        sh[u][hh] = hidden[(b0 + u) * HSZ + hh];
    }
    __syncthreads();

    for (int j = w; j < K3H; j += 8) {
        const float* wi = W_ih + (size_t)j * ESZ;
        const float* wh = W_hh + (size_t)j * HSZ;
        float si0 = 0.f, si1 = 0.f, sg0 = 0.f, sg1 = 0.f;
        #pragma unroll
        for (int i = lane; i < ESZ; i += 32) {
            float wv = wi[i];
            si0 += wv * sx[0][i]; si1 += wv * sx[1][i];
        }
        #pragma unroll
        for (int i = lane; i < HSZ; i += 32) {
            float wv = wh[i];
            sg0 += wv * sh[0][i]; sg1 += wv * sh[1][i];
        }
        si0 = warp_sum(si0); si1 = warp_sum(si1);
        sg0 = warp_sum(sg0); sg1 = warp_sum(sg1);
        if (lane == 0) {
            float bi = b_ih[j], bh = b_hh[j];
            sgi[0][j] = si0 + bi; sgi[1][j] = si1 + bi;
            sgh[0][j] = sg0 + bh; sgh[1][j] = sg1 + bh;
        }
    }
    __syncthreads();

    #pragma unroll
    for (int i = t; i < 2 * HSZ; i += 256) {
        int u = i >> 9, hh = i & (HSZ - 1);
        float r = 1.f / (1.f + expf(-(sgi[u][hh] + sgh[u][hh])));
        float z = 1.f / (1.f + expf(-(sgi[u][hh + HSZ] + sgh[u][hh + HSZ])));
        float n = tanhf(sgi[u][hh + 2 * HSZ] + r * sgh[u][hh + 2 * HSZ]);
        float hn = (1.f - z) * n + z * sh[u][hh];
        shn[u][hh] = hn;
        h_out[(b0 + u) * HSZ + hh] = hn;
        g_nh[(b0 + u) * K3H + HSZ + hh] = hn;
    }
    __syncthreads();

    for (int j = w; j < HSZ; j += 8) {
        const float* wa = W_ae + (size_t)j * HSZ;
        const float* wd = W_ad + (size_t)j * HSZ;
        float a0 = 0.f, a1 = 0.f, d0 = 0.f, d1 = 0.f;
        #pragma unroll
        for (int i = lane; i < HSZ; i += 32) {
            float av = wa[i], dv = wd[i];
            a0 += av * shn[0][i]; a1 += av * shn[1][i];
            d0 += dv * shn[0][i]; d1 += dv * shn[1][i];
        }
        a0 = warp_sum(a0); a1 = warp_sum(a1);
        d0 = warp_sum(d0); d1 = warp_sum(d1);
        if (lane == 0) {
            float ba = b_ae[j], bd = b_ad[j];
            g_te[b0 * HSZ + j] = a0 + ba; g_te[(b0 + 1) * HSZ + j] = a1 + ba;
            g_td[b0 * HSZ + j] = d0 + bd; g_td[(b0 + 1) * HSZ + j] = d1 + bd;
        }
    }
}

// ---------------- K2: attention -----------------------------------------------
template<int S, int NHOFF, bool USE_TD, bool MASK, bool STORE_ALPHA>
__global__ void __launch_bounds__(512) k_attn(
    const float* __restrict__ kv,
    const int* __restrict__ lengths)
{
    __shared__ float sq[HSZ];
    __shared__ float sc[S];
    __shared__ float sred[512];

    const int b = blockIdx.x;
    const int t = threadIdx.x;
    const int w = t >> 5, lane = t & 31;

    const float* q = USE_TD ? g_td : g_te;
    sq[t] = q[b * HSZ + t];
    __syncthreads();

    int len = MASK ? lengths[b] : S;

    for (int l = w; l < S; l += 16) {
        const float* row = kv + ((size_t)l * BSZ + b) * HSZ;
        float s = 0.f;
        #pragma unroll 4
        for (int i = lane; i < HSZ; i += 32) s += row[i] * sq[i];
        s = warp_sum(s);
        if (lane == 0) {
            if (MASK && (S < len) && (l >= len)) s = -INFINITY;
            sc[l] = s;
        }
    }
    __syncthreads();

    float v = (t < S) ? sc[t] : -INFINITY;
    sred[t] = v; __syncthreads();
    #pragma unroll
    for (int o = 256; o > 0; o >>= 1) { if (t < o) sred[t] = fmaxf(sred[t], sred[t + o]); __syncthreads(); }
    float m = sred[0]; __syncthreads();
    float e = (t < S) ? expf(sc[t] - m) : 0.f;
    sred[t] = e; __syncthreads();
    #pragma unroll
    for (int o = 256; o > 0; o >>= 1) { if (t < o) sred[t] += sred[t + o]; __syncthreads(); }
    float ssum = sred[0]; __syncthreads();
    if (t < S) {
        float a = e / ssum;
        sc[t] = a;
        if (STORE_ALPHA) g_alpha[b * S + t] = a;
    }
    __syncthreads();

    float c = 0.f;
    const float* base = kv + (size_t)b * HSZ + t;
    #pragma unroll 4
    for (int l = 0; l < S; l++) c += sc[l] * base[(size_t)l * BSZ * HSZ];
    g_nh[b * K3H + NHOFF + t] = c;
}

// ---------------- K3: pointer prob (block per b) --------------------------------
__global__ void __launch_bounds__(256) k_pointer(
    const float* __restrict__ W_ptr, const float* __restrict__ b_ptr)
{
    __shared__ float sred[8];
    const int b = blockIdx.x;
    const int t = threadIdx.x;
    const int w = t >> 5, lane = t & 31;
    float s = 0.f;
    #pragma unroll
    for (int i = t; i < K3H; i += 256) s += g_nh[b * K3H + i] * W_ptr[i];
    s = warp_sum(s);
    if (lane == 0) sred[w] = s;
    __syncthreads();
    if (t == 0) {
        float tot = 0.f;
        #pragma unroll
        for (int i = 0; i < 8; i++) tot += sred[i];
        g_p[b] = tot + b_ptr[0];
    }
}

// ---------------- K4: bf16 mma.sync GEMM: logits = nh @ W^T + bias --------------
// Block 128(M) x 128(N) x 32(K). 8 warps (2m x 4n), warp tile 64x32.
// Smem layout [row][kpair] with row stride 20 words: frag LDS pattern
// bank(g,tig) = (20g + tig) mod 32 covers all 32 banks -> conflict-free.
#define GBN 128
#define GBK 32
#define NKT (K3H / GBK)     // 48
#define AST 20              // row stride in 32-bit words (16 used + 4 pad)
#define TBUF (BSZ * AST)    // 2560 words per tile buffer

__device__ __forceinline__ void mma_bf16(float* d, const uint32_t* a, const uint32_t* b) {
    asm volatile(
        "mma.sync.aligned.m16n8k16.row.col.f32.bf16.bf16.f32 "
        "{%0,%1,%2,%3}, {%4,%5,%6,%7}, {%8,%9}, {%0,%1,%2,%3};\n"
        : "+f"(d[0]), "+f"(d[1]), "+f"(d[2]), "+f"(d[3])
        : "r"(a[0]), "r"(a[1]), "r"(a[2]), "r"(a[3]), "r"(b[0]), "r"(b[1]));
}

__global__ void __launch_bounds__(256) k_gemm_bf16(
    const float* __restrict__ W,        // (V, K3H)
    const float* __restrict__ bias,     // (V,)
    float* __restrict__ out)            // (B, V)
{
    __shared__ uint32_t sa[2][TBUF];
    __shared__ uint32_t sb[2][TBUF];

    const int tid  = threadIdx.x;
    const int warp = tid >> 5, lane = tid & 31;
    const int g    = lane >> 2, tig = lane & 3;
    const int wm   = (warp >> 2) * 64;   // 0 / 64
    const int wn   = (warp & 3) * 32;    // 0..96
    const int n0   = blockIdx.x * GBN;

    // staging: thread -> (row = tid>>1, k-half = (tid&1)*16 floats)
    const int srow = tid >> 1;
    const int shalf = (tid & 1);
    const bool bvalid = (n0 + srow) < VSZ;
    const float* aptr = g_nh + (size_t)srow * K3H + shalf * 16;
    const float* bptr = W + (size_t)(n0 + srow) * K3H + shalf * 16;

    uint32_t pa[8], pb[8];              // packed bf16x2 staged in regs

    auto ldg_pack = [&](int kt) {
        const float4* a4 = (const float4*)(aptr + kt * GBK);
        #pragma unroll
        for (int q = 0; q < 4; q++) {
            float4 v = a4[q];
            __nv_bfloat162 lo = __floats2bfloat162_rn(v.x, v.y);
            __nv_bfloat162 hi = __floats2bfloat162_rn(v.z, v.w);
            pa[2 * q]     = *(uint32_t*)&lo;
            pa[2 * q + 1] = *(uint32_t*)&hi;
        }
        if (bvalid) {
            const float4* b4 = (const float4*)(bptr + kt * GBK);
            #pragma unroll
            for (int q = 0; q < 4; q++) {
                float4 v = b4[q];
                __nv_bfloat162 lo = __floats2bfloat162_rn(v.x, v.y);
                __nv_bfloat162 hi = __floats2bfloat162_rn(v.z, v.w);
                pb[2 * q]     = *(uint32_t*)&lo;
                pb[2 * q + 1] = *(uint32_t*)&hi;
            }
        } else {
            #pragma unroll
            for (int q = 0; q < 8; q++) pb[q] = 0u;
        }
    };
    auto sts = [&](int buf) {
        uint32_t* A = &sa[buf][srow * AST + shalf * 8];
        uint32_t* B = &sb[buf][srow * AST + shalf * 8];
        *(uint4*)(A)     = make_uint4(pa[0], pa[1], pa[2], pa[3]);
        *(uint4*)(A + 4) = make_uint4(pa[4], pa[5], pa[6], pa[7]);
        *(uint4*)(B)     = make_uint4(pb[0], pb[1], pb[2], pb[3]);
        *(uint4*)(B + 4) = make_uint4(pb[4], pb[5], pb[6], pb[7]);
    };

    float acc[4][4][4];
    #pragma unroll
    for (int mi = 0; mi < 4; mi++)
        #pragma unroll
        for (int nf = 0; nf < 4; nf++)
            #pragma unroll
            for (int r = 0; r < 4; r++) acc[mi][nf][r] = 0.f;

    ldg_pack(0);
    sts(0);
    __syncthreads();

    for (int t = 0; t < NKT; t++) {
        const int cur = t & 1;
        if (t + 1 < NKT) ldg_pack(t + 1);        // overlap LDG with mma

        #pragma unroll
        for (int kh = 0; kh < 2; kh++) {
            const int kb = kh * 8 + tig;
            uint32_t bf[4][2];
            #pragma unroll
            for (int nf = 0; nf < 4; nf++) {
                const int r = wn + nf * 8 + g;
                bf[nf][0] = sb[cur][r * AST + kb];
                bf[nf][1] = sb[cur][r * AST + kb + 4];
            }
            #pragma unroll
            for (int mi = 0; mi < 4; mi++) {
                const int r0 = wm + mi * 16 + g;
                uint32_t af[4];
                af[0] = sa[cur][r0 * AST + kb];
                af[1] = sa[cur][(r0 + 8) * AST + kb];
                af[2] = sa[cur][r0 * AST + kb + 4];
                af[3] = sa[cur][(r0 + 8) * AST + kb + 4];
                #pragma unroll
                for (int nf = 0; nf < 4; nf++) mma_bf16(acc[mi][nf], af, bf[nf]);
            }
        }

        if (t + 1 < NKT) {
            sts((t + 1) & 1);      // other buffer: safe, prior sync retired its readers
            __syncthreads();
        }
    }

    // epilogue: bias + store (float2 per lane)
    #pragma unroll
    for (int mi = 0; mi < 4; mi++) {
        const int m = wm + mi * 16 + g;
        #pragma unroll
        for (int nf = 0; nf < 4; nf++) {
            const int gn = n0 + wn + nf * 8 + 2 * tig;
            if (gn < VSZ) {
                float2 bv = *(const float2*)(bias + gn);
                float2 o0 = { acc[mi][nf][0] + bv.x, acc[mi][nf][1] + bv.y };
                float2 o1 = { acc[mi][nf][2] + bv.x, acc[mi][nf][3] + bv.y };
                *(float2*)(out + (size_t)m * VSZ + gn) = o0;
                *(float2*)(out + (size_t)(m + 8) * VSZ + gn) = o1;
            }
        }
    }
}

// ---------------- K5: per-row logsumexp over V ---------------------------------
__global__ void __launch_bounds__(1024) k_lse(const float* __restrict__ logits)
{
    __shared__ float sr[1024];
    const int b = blockIdx.x, t = threadIdx.x;
    const float* row = logits + (size_t)b * VSZ;
    float m = -INFINITY;
    for (int i = t; i < VSZ; i += 1024) m = fmaxf(m, row[i]);
    sr[t] = m; __syncthreads();
    #pragma unroll
    for (int o = 512; o > 0; o >>= 1) { if (t < o) sr[t] = fmaxf(sr[t], sr[t + o]); __syncthreads(); }
    m = sr[0]; __syncthreads();
    float s = 0.f;
    for (int i = t; i < VSZ; i += 1024) s += expf(row[i] - m);
    sr[t] = s; __syncthreads();
    #pragma unroll
    for (int o = 512; o > 0; o >>= 1) { if (t < o) sr[t] += sr[t + o]; __syncthreads(); }
    if (t == 0) g_lse[b] = m + logf(sr[0]);
}

// ---------------- K6: finalize -------------------------------------------------
__global__ void __launch_bounds__(256) k_finalize(float* __restrict__ out)
{
    size_t i = (size_t)blockIdx.x * blockDim.x + threadIdx.x;
    if (i >= (size_t)BSZ * VSZ) return;
    int b = (int)(i / VSZ);
    out[i] = (1.f - g_p[b]) * (out[i] - g_lse[b]);
}

// ---------------- K7: pointer scatter add --------------------------------------
__global__ void __launch_bounds__(256) k_scatter(
    float* __restrict__ out, const int* __restrict__ enc_inputs)
{
    int i = blockIdx.x * blockDim.x + threadIdx.x;
    if (i >= BSZ * LSZ) return;
    int b = i & (BSZ - 1);
    int l = i >> 7;
    int tok = enc_inputs[l * BSZ + b];
    atomicAdd(out + (size_t)b * VSZ + tok, g_p[b] * g_alpha[b * LSZ + l]);
}

// ---------------- launch --------------------------------------------------------
extern "C" void kernel_launch(void* const* d_in, const int* in_sizes, int n_in,
                              void* d_out, int out_size)
{
    const int*   inputs      = (const int*)  d_in[0];
    const float* hidden      = (const float*)d_in[1];
    const float* enc_hidden  = (const float*)d_in[2];
    const int*   enc_lengths = (const int*)  d_in[3];
    const float* prev_w      = (const float*)d_in[4];
    const float* dec_hidden  = (const float*)d_in[5];
    const int*   enc_inputs  = (const int*)  d_in[6];

    int wbase = 7;
    for (int i = 7; i < n_in; i++) {
        if (in_sizes[i] == VSZ * ESZ) { wbase = i; break; }
    }
    const float* emb   = (const float*)d_in[wbase + 0];
    const float* W_ih  = (const float*)d_in[wbase + 1];
    const float* W_hh  = (const float*)d_in[wbase + 2];
    const float* b_ih  = (const float*)d_in[wbase + 3];
    const float* b_hh  = (const float*)d_in[wbase + 4];
    const float* W_ae  = (const float*)d_in[wbase + 5];
    const float* b_ae  = (const float*)d_in[wbase + 6];
    const float* W_ad  = (const float*)d_in[wbase + 7];
    const float* b_ad  = (const float*)d_in[wbase + 8];
    const float* W_ptr = (const float*)d_in[wbase + 9];
    const float* b_ptr = (const float*)d_in[wbase + 10];
    const float* W_out = (const float*)d_in[wbase + 11];
    const float* b_out = (const float*)d_in[wbase + 12];

    float* out     = (float*)d_out;
    float* h_out   = out + (size_t)BSZ * VSZ;
    float* pw_out  = h_out + (size_t)BSZ * HSZ;

    k_gru<<<BSZ / 2, 256>>>(inputs, hidden, emb, W_ih, W_hh, b_ih, b_hh,
                            W_ae, b_ae, W_ad, b_ad, h_out);

    k_attn<LSZ, 0,       false, true,  true ><<<BSZ, 512>>>(enc_hidden, enc_lengths);
    k_attn<TSZ, 2 * HSZ, true,  false, false><<<BSZ, 512>>>(dec_hidden, enc_lengths);

    k_pointer<<<BSZ, 256>>>(W_ptr, b_ptr);

    k_gemm_bf16<<<(VSZ + GBN - 1) / GBN, 256>>>(W_out, b_out, out);

    k_lse<<<BSZ, 1024>>>(out);

    k_finalize<<<(int)(((size_t)BSZ * VSZ + 255) / 256), 256>>>(out);

    k_scatter<<<(BSZ * LSZ + 255) / 256, 256>>>(out, enc_inputs);

    cudaMemcpyAsync(pw_out, prev_w, (size_t)BSZ * LSZ * sizeof(float),
                    cudaMemcpyDeviceToDevice, 0);
}